// round 14
// baseline (speedup 1.0000x reference)
#include <cuda_runtime.h>
#include <cuda_bf16.h>
#include <cstdint>

#define Nn 50000
#define Ee 800000
#define Hh 256
#define NLAYERS 3
#define MP 68     // Xs row stride (floats) for FFMA kernels
#define KT 32     // K tile (FFMA path)
#define NB_IN 782 // input-projection blocks inside k_prep
#define NB_W  3840 // weight-fragmentize blocks (3 layers x 5 sets x 65536 / 256)

// ---------------- scratch (no allocs allowed -> device globals) ----------------
static __device__ float g_h  [(size_t)Nn*Hh];
static __device__ float g_P  [(size_t)Nn*Hh];
static __device__ float g_Q  [(size_t)Nn*Hh];
static __device__ float g_agg[(size_t)Nn*Hh];
static __device__ float g_U  [(size_t)Nn*Hh];
static __device__ float g_lut[41*Hh];
// weights (hi split) in mma-fragment order, 5 sets per layer:
// which: 0=e2(edge), 1=e1 P, 2=e1 Q, 3=n1 h, 4=n1 agg
// [li][which][s=k/16][jp=n/16][lane][tb][word][half]  (uint4 per lane)
static __device__ __nv_bfloat16 g_wF[(size_t)3*5*16*16*32*8];

#define LUT_REL  0
#define LUT_RS   (8*Hh)
#define LUT_RD   (16*Hh)
#define LUT_CS   (24*Hh)
#define LUT_CD   (27*Hh)
#define LUT_NR   (30*Hh)
#define LUT_NC   (38*Hh)

__device__ __forceinline__ float silu_f(float x) {
    return __fdividef(x, 1.0f + __expf(-x));
}
__device__ __forceinline__ void red_add_v4(float* p, float4 v) {
    asm volatile("red.global.add.v4.f32 [%0], {%1,%2,%3,%4};"
                 :: "l"(p), "f"(v.x), "f"(v.y), "f"(v.z), "f"(v.w) : "memory");
}
__device__ __forceinline__ uint32_t smem_u32(const void* p) {
    uint32_t a;
    asm("{ .reg .u64 t; cvta.to.shared.u64 t, %1; cvt.u32.u64 %0, t; }" : "=r"(a) : "l"(p));
    return a;
}

// ---- Ampere-path tensor ops (plain sm_103-legal) ----
__device__ __forceinline__ void ldsm4(uint32_t (&r)[4], uint32_t addr) {
    asm volatile("ldmatrix.sync.aligned.m8n8.x4.shared.b16 {%0,%1,%2,%3}, [%4];"
                 : "=r"(r[0]), "=r"(r[1]), "=r"(r[2]), "=r"(r[3]) : "r"(addr));
}
__device__ __forceinline__ void mma16816(float (&d)[4], const uint32_t (&a)[4],
                                         uint32_t b0, uint32_t b1) {
    asm volatile(
        "mma.sync.aligned.m16n8k16.row.col.f32.bf16.bf16.f32 "
        "{%0,%1,%2,%3}, {%4,%5,%6,%7}, {%8,%9}, {%0,%1,%2,%3};"
        : "+f"(d[0]), "+f"(d[1]), "+f"(d[2]), "+f"(d[3])
        : "r"(a[0]), "r"(a[1]), "r"(a[2]), "r"(a[3]), "r"(b0), "r"(b1));
}

// packed f32x2 helpers (FFMA2 path: k_n2 / k_out)
__device__ __forceinline__ unsigned long long dup2(float x) {
    unsigned long long r;
    asm("mov.b64 %0, {%1,%1};" : "=l"(r) : "f"(x));
    return r;
}
__device__ __forceinline__ void fma2(unsigned long long& a, unsigned long long t,
                                     unsigned long long w) {
    asm("fma.rn.f32x2 %0, %1, %2, %0;" : "+l"(a) : "l"(t), "l"(w));
}
__device__ __forceinline__ void unpack2(unsigned long long u, float& a, float& b) {
    asm("mov.b64 {%0,%1}, %2;" : "=f"(a), "=f"(b) : "l"(u));
}

// ---------------- merged prep kernel: input projection + weight fragmentize ----
__global__ void k_prep(const float* __restrict__ scalars,
                       const int* __restrict__ colr, const int* __restrict__ role,
                       const float* __restrict__ cemb, const float* __restrict__ remb,
                       const float* __restrict__ in_w, const float* __restrict__ in_b,
                       const float* __restrict__ e2w, const float* __restrict__ e1w,
                       const float* __restrict__ n1w) {
    if (blockIdx.x < NB_IN) {
        int node0 = blockIdx.x * 64;
        int n = threadIdx.x;
        for (int mi = 0; mi < 64; mi++) {
            int node = node0 + mi;
            if (node >= Nn) return;
            float acc = in_b[n];
            const float* s = scalars + (size_t)node*16;
            #pragma unroll
            for (int k = 0; k < 16; k++) acc += s[k]*in_w[k*Hh + n];
            const float* ce = cemb + colr[node]*8;
            #pragma unroll
            for (int k = 0; k < 8; k++) acc += ce[k]*in_w[(16+k)*Hh + n];
            const float* re = remb + role[node]*8;
            #pragma unroll
            for (int k = 0; k < 8; k++) acc += re[k]*in_w[(24+k)*Hh + n];
            g_h[(size_t)node*Hh + n] = acc;
        }
    } else {
        int idx = (blockIdx.x - NB_IN) * 256 + threadIdx.x;
        if (idx >= 3*5*65536) return;
        int li = idx / (5*65536);
        int r = idx % (5*65536);
        int which = r >> 16;
        int t = r & 65535;
        int k = t >> 8, n = t & 255;
        float w;
        if      (which == 0) w = e2w[(size_t)li*65536 + k*256 + n];
        else if (which == 1) w = e1w[(size_t)li*560*256 + k*256 + n];
        else if (which == 2) w = e1w[(size_t)li*560*256 + (size_t)(k+256)*256 + n];
        else if (which == 3) w = n1w[(size_t)li*528*256 + k*256 + n];
        else                 w = n1w[(size_t)li*528*256 + (size_t)(k+256)*256 + n];
        __nv_bfloat16 hi = __float2bfloat16(w);
        int s = k >> 4, jp = n >> 4, tb = (n >> 3) & 1;
        int lane = ((n & 7) << 2) | ((k & 7) >> 1);
        int word = (k >> 3) & 1, half = k & 1;
        size_t bi = (((size_t)(li*5 + which)*16 + s)*16 + jp)*32 + lane;
        g_wF[bi*8 + tb*4 + word*2 + half] = hi;
    }
}

// ---------------- shared HMMA machinery ----------------------------------------
#define EOFF_IDX  0
#define EOFF_BIAS 768
#define EOFF_AHI  1792                    // 64*528 = 33792
#define EOFF_ALO  (1792 + 33792)          // 35584
#define ASTRIDE   528
#define SMEM_TC   (35584 + 33792)         // 69376

// 16 k-steps of the 2-term mainloop for one 128-col output half (node kernels).
__device__ __forceinline__ void tc_mainloop(uint32_t ahi_base, uint32_t alo_base,
                                            const uint4* __restrict__ whi, int jp0,
                                            float (&acc)[2][4][4]) {
    #pragma unroll
    for (int s = 0; s < 16; s++) {
        int kg = s * 16;
        uint32_t ah[2][4], al[2][4];
        ldsm4(ah[0], ahi_base + kg*2);
        ldsm4(ah[1], ahi_base + 16*ASTRIDE + kg*2);
        ldsm4(al[0], alo_base + kg*2);
        ldsm4(al[1], alo_base + 16*ASTRIDE + kg*2);
        uint4 bh0 = whi[(s*16 + jp0    )*32];
        uint4 bh1 = whi[(s*16 + jp0 + 1)*32];
        #pragma unroll
        for (int mt = 0; mt < 2; mt++) {
            mma16816(acc[mt][0], ah[mt], bh0.x, bh0.y);
            mma16816(acc[mt][1], ah[mt], bh0.z, bh0.w);
            mma16816(acc[mt][2], ah[mt], bh1.x, bh1.y);
            mma16816(acc[mt][3], ah[mt], bh1.z, bh1.w);
        }
        #pragma unroll
        for (int mt = 0; mt < 2; mt++) {
            mma16816(acc[mt][0], al[mt], bh0.x, bh0.y);
            mma16816(acc[mt][1], al[mt], bh0.z, bh0.w);
            mma16816(acc[mt][2], al[mt], bh1.x, bh1.y);
            mma16816(acc[mt][3], al[mt], bh1.z, bh1.w);
        }
    }
}

// edge variant: explicit B register prefetch one k-step ahead
__device__ __forceinline__ void tc_mainloop_pf(uint32_t ahi_base, uint32_t alo_base,
                                               const uint4* __restrict__ whi, int jp0,
                                               float (&acc)[2][4][4]) {
    uint4 b0 = whi[(jp0    )*32];
    uint4 b1 = whi[(jp0 + 1)*32];
    #pragma unroll
    for (int s = 0; s < 16; s++) {
        int kg = s * 16;
        uint32_t ah[2][4], al[2][4];
        ldsm4(ah[0], ahi_base + kg*2);
        ldsm4(ah[1], ahi_base + 16*ASTRIDE + kg*2);
        ldsm4(al[0], alo_base + kg*2);
        ldsm4(al[1], alo_base + 16*ASTRIDE + kg*2);
        uint4 nb0, nb1;
        if (s < 15) {
            nb0 = whi[((s+1)*16 + jp0    )*32];
            nb1 = whi[((s+1)*16 + jp0 + 1)*32];
        }
        #pragma unroll
        for (int mt = 0; mt < 2; mt++) {
            mma16816(acc[mt][0], ah[mt], b0.x, b0.y);
            mma16816(acc[mt][1], ah[mt], b0.z, b0.w);
            mma16816(acc[mt][2], ah[mt], b1.x, b1.y);
            mma16816(acc[mt][3], ah[mt], b1.z, b1.w);
        }
        #pragma unroll
        for (int mt = 0; mt < 2; mt++) {
            mma16816(acc[mt][0], al[mt], b0.x, b0.y);
            mma16816(acc[mt][1], al[mt], b0.z, b0.w);
            mma16816(acc[mt][2], al[mt], b1.x, b1.y);
            mma16816(acc[mt][3], al[mt], b1.z, b1.w);
        }
        if (s < 15) { b0 = nb0; b1 = nb1; }
    }
}

// build A hi/lo from contiguous node rows (64 rows, 256 threads)
__device__ __forceinline__ void build_A_node(float* __restrict__ src, int row0,
                                             char* __restrict__ smem, bool clear) {
    int tid = threadIdx.x;
    int k0 = (tid & 127) * 2, mh = tid >> 7;
    char* ahi = smem + EOFF_AHI;
    char* alo = smem + EOFF_ALO;
    #pragma unroll 4
    for (int m = mh*32; m < mh*32 + 32; m++) {
        int node = row0 + m; if (node > Nn-1) node = Nn-1;
        float2 v = *(const float2*)(src + (size_t)node*256 + k0);
        __nv_bfloat16 h0 = __float2bfloat16(v.x), h1 = __float2bfloat16(v.y);
        uint32_t hw = ((uint32_t)__bfloat16_as_ushort(h1) << 16)
                    | (uint32_t)__bfloat16_as_ushort(h0);
        float r0 = v.x - __bfloat162float(h0), r1 = v.y - __bfloat162float(h1);
        uint32_t lw;
        asm("cvt.rn.bf16x2.f32 %0, %1, %2;" : "=r"(lw) : "f"(r1), "f"(r0));
        *(uint32_t*)(ahi + m*ASTRIDE + k0*2) = hw;
        *(uint32_t*)(alo + m*ASTRIDE + k0*2) = lw;
        if (clear) *(float2*)(src + (size_t)node*256 + k0) = make_float2(0.f, 0.f);
    }
}

// ---------------- HMMA edge kernel (R12 shape + B prefetch) ---------------------
__global__ void __launch_bounds__(256, 2)
k_edge_mma(const int* __restrict__ src, const int* __restrict__ dst,
           const int* __restrict__ rel, const float* __restrict__ e2b, int li) {
    extern __shared__ char smem[];
    uint32_t sb = smem_u32(smem);
    int tid = threadIdx.x, wid = tid >> 5, lane = tid & 31;
    int* ss = (int*)(smem + EOFF_IDX);
    int* ds = ss + 64;
    int* rr = ds + 64;
    float* bias = (float*)(smem + EOFF_BIAS);
    int e0 = blockIdx.x * 64;

    if (tid < 64) { ss[tid] = src[e0+tid]; ds[tid] = dst[e0+tid]; rr[tid] = rel[e0+tid]; }
    bias[tid] = e2b[li*256 + tid];
    __syncthreads();

    // build A hi/lo [m][k] from gathered P/Q/lut + silu
    {
        int k0 = (tid & 127) * 2, mh = tid >> 7;
        char* ahi = smem + EOFF_AHI;
        char* alo = smem + EOFF_ALO;
        #pragma unroll 4
        for (int m = mh*32; m < mh*32 + 32; m++) {
            int si = ss[m], di = ds[m], ri = rr[m];
            float2 p = *(const float2*)(g_P + (size_t)si*256 + k0);
            float2 q = *(const float2*)(g_Q + (size_t)di*256 + k0);
            float2 l = *(const float2*)(g_lut + LUT_REL + ri*256 + k0);
            float v0 = silu_f(p.x + q.x + l.x);
            float v1 = silu_f(p.y + q.y + l.y);
            __nv_bfloat16 h0 = __float2bfloat16(v0), h1 = __float2bfloat16(v1);
            uint32_t hw = ((uint32_t)__bfloat16_as_ushort(h1) << 16)
                        | (uint32_t)__bfloat16_as_ushort(h0);
            float r0 = v0 - __bfloat162float(h0), r1 = v1 - __bfloat162float(h1);
            uint32_t lw;
            asm("cvt.rn.bf16x2.f32 %0, %1, %2;" : "=r"(lw) : "f"(r1), "f"(r0));
            *(uint32_t*)(ahi + m*ASTRIDE + k0*2) = hw;
            *(uint32_t*)(alo + m*ASTRIDE + k0*2) = lw;
        }
    }
    __syncthreads();

    int wm = wid >> 2, wn = wid & 3;
    int a_row = (lane & 15), a_col = (lane >> 4) << 3;
    uint32_t ahi_base = sb + EOFF_AHI + (wm*32 + a_row)*ASTRIDE + a_col*2;
    uint32_t alo_base = sb + EOFF_ALO + (wm*32 + a_row)*ASTRIDE + a_col*2;
    const uint4* whi = ((const uint4*)g_wF) + (size_t)(li*5 + 0)*8192 + lane;

    #pragma unroll
    for (int nh = 0; nh < 2; nh++) {
        float acc[2][4][4];
        #pragma unroll
        for (int a = 0; a < 2; a++)
            #pragma unroll
            for (int b = 0; b < 4; b++)
                #pragma unroll
                for (int c = 0; c < 4; c++) acc[a][b][c] = 0.f;
        tc_mainloop_pf(ahi_base, alo_base, whi, nh*8 + wn*2, acc);

        #pragma unroll
        for (int mt = 0; mt < 2; mt++) {
            int mlo = wm*32 + mt*16 + (lane >> 2);
            int mhi = mlo + 8;
            float* rowlo = g_agg + (size_t)ds[mlo] * 256;
            float* rowhi = g_agg + (size_t)ds[mhi] * 256;
            #pragma unroll
            for (int nt = 0; nt < 4; nt++) {
                int col = nh*128 + wn*32 + nt*8 + (lane & 3)*2;
                float s0 = silu_f(acc[mt][nt][0] + bias[col]);
                float s1 = silu_f(acc[mt][nt][1] + bias[col+1]);
                float s2 = silu_f(acc[mt][nt][2] + bias[col]);
                float s3 = silu_f(acc[mt][nt][3] + bias[col+1]);
                float p0 = __shfl_xor_sync(0xffffffffu, s0, 1);
                float p1 = __shfl_xor_sync(0xffffffffu, s1, 1);
                float p2 = __shfl_xor_sync(0xffffffffu, s2, 1);
                float p3 = __shfl_xor_sync(0xffffffffu, s3, 1);
                if (!(lane & 1)) {
                    red_add_v4(rowlo + col, make_float4(s0, s1, p0, p1));
                    red_add_v4(rowhi + col, make_float4(s2, s3, p2, p3));
                }
            }
        }
    }
}

// ---------------- HMMA P/Q kernel: one A-build serves 4 output halves ----------
__global__ void __launch_bounds__(256, 2)
k_pq_mma(const int* __restrict__ role, const int* __restrict__ colr, int li) {
    extern __shared__ char smem[];
    uint32_t sb = smem_u32(smem);
    int tid = threadIdx.x, wid = tid >> 5, lane = tid & 31;
    int* rs = (int*)(smem + EOFF_IDX);
    int* cs = rs + 64;
    int row0 = blockIdx.x * 64;

    if (tid < 64) {
        int r = row0 + tid; if (r > Nn-1) r = Nn-1;
        rs[tid] = role[r]; cs[tid] = colr[r];
    }
    __syncthreads();
    build_A_node(g_h, row0, smem, false);
    __syncthreads();

    int wm = wid >> 2, wn = wid & 3;
    int a_row = (lane & 15), a_col = (lane >> 4) << 3;
    uint32_t ahi_base = sb + EOFF_AHI + (wm*32 + a_row)*ASTRIDE + a_col*2;
    uint32_t alo_base = sb + EOFF_ALO + (wm*32 + a_row)*ASTRIDE + a_col*2;

    #pragma unroll
    for (int half = 0; half < 4; half++) {
        int which = (half < 2) ? 1 : 2;     // P : Q
        int nh = half & 1;
        const uint4* whi = ((const uint4*)g_wF) + (size_t)(li*5 + which)*8192 + lane;
        float acc[2][4][4];
        #pragma unroll
        for (int a = 0; a < 2; a++)
            #pragma unroll
            for (int b = 0; b < 4; b++)
                #pragma unroll
                for (int c = 0; c < 4; c++) acc[a][b][c] = 0.f;
        tc_mainloop(ahi_base, alo_base, whi, nh*8 + wn*2, acc);

        float* out = (half < 2) ? g_P : g_Q;
        const float* lutR = g_lut + ((half < 2) ? LUT_RS : LUT_RD);
        const float* lutC = g_lut + ((half < 2) ? LUT_CS : LUT_CD);
        #pragma unroll
        for (int mt = 0; mt < 2; mt++) {
            #pragma unroll
            for (int hh = 0; hh < 2; hh++) {
                int m = wm*32 + mt*16 + (lane >> 2) + hh*8;
                int node = row0 + m;
                if (node >= Nn) continue;
                const float* lr = lutR + rs[m]*256;
                const float* lc = lutC + cs[m]*256;
                float* orow = out + (size_t)node*256;
                #pragma unroll
                for (int nt = 0; nt < 4; nt++) {
                    int col = nh*128 + wn*32 + nt*8 + (lane & 3)*2;
                    float2 l1 = *(const float2*)(lr + col);
                    float2 l2 = *(const float2*)(lc + col);
                    float2 v;
                    v.x = acc[mt][nt][hh*2+0] + l1.x + l2.x;
                    v.y = acc[mt][nt][hh*2+1] + l1.y + l2.y;
                    *(float2*)(orow + col) = v;
                }
            }
        }
    }
}

// ---------------- HMMA n1 kernel: K=512 (h then agg), clears agg ----------------
__global__ void __launch_bounds__(256, 2)
k_n1_mma(const int* __restrict__ role, const int* __restrict__ colr, int li) {
    extern __shared__ char smem[];
    uint32_t sb = smem_u32(smem);
    int tid = threadIdx.x, wid = tid >> 5, lane = tid & 31;
    int* rs = (int*)(smem + EOFF_IDX);
    int* cs = rs + 64;
    int row0 = blockIdx.x * 64;

    if (tid < 64) {
        int r = row0 + tid; if (r > Nn-1) r = Nn-1;
        rs[tid] = role[r]; cs[tid] = colr[r];
    }

    int wm = wid >> 2, wn = wid & 3;
    int a_row = (lane & 15), a_col = (lane >> 4) << 3;
    uint32_t ahi_base = sb + EOFF_AHI + (wm*32 + a_row)*ASTRIDE + a_col*2;
    uint32_t alo_base = sb + EOFF_ALO + (wm*32 + a_row)*ASTRIDE + a_col*2;

    #pragma unroll
    for (int nh = 0; nh < 2; nh++) {
        float acc[2][4][4];
        #pragma unroll
        for (int a = 0; a < 2; a++)
            #pragma unroll
            for (int b = 0; b < 4; b++)
                #pragma unroll
                for (int c = 0; c < 4; c++) acc[a][b][c] = 0.f;

        __syncthreads();
        build_A_node(g_h, row0, smem, false);
        __syncthreads();
        {
            const uint4* whi = ((const uint4*)g_wF) + (size_t)(li*5 + 3)*8192 + lane;
            tc_mainloop(ahi_base, alo_base, whi, nh*8 + wn*2, acc);
        }
        __syncthreads();
        build_A_node(g_agg, row0, smem, nh == 1);   // clear agg on last pass
        __syncthreads();
        {
            const uint4* whi = ((const uint4*)g_wF) + (size_t)(li*5 + 4)*8192 + lane;
            tc_mainloop(ahi_base, alo_base, whi, nh*8 + wn*2, acc);
        }

        #pragma unroll
        for (int mt = 0; mt < 2; mt++) {
            #pragma unroll
            for (int hh = 0; hh < 2; hh++) {
                int m = wm*32 + mt*16 + (lane >> 2) + hh*8;
                int node = row0 + m;
                if (node >= Nn) continue;
                const float* lr = g_lut + LUT_NR + rs[m]*256;
                const float* lc = g_lut + LUT_NC + cs[m]*256;
                float* orow = g_U + (size_t)node*256;
                #pragma unroll
                for (int nt = 0; nt < 4; nt++) {
                    int col = nh*128 + wn*32 + nt*8 + (lane & 3)*2;
                    float2 l1 = *(const float2*)(lr + col);
                    float2 l2 = *(const float2*)(lc + col);
                    float2 v;
                    v.x = silu_f(acc[mt][nt][hh*2+0] + l1.x + l2.x);
                    v.y = silu_f(acc[mt][nt][hh*2+1] + l1.y + l2.y);
                    *(float2*)(orow + col) = v;
                }
            }
        }
    }
}

// ---------------- FFMA-path machinery (k_n2 / k_out) ----------------------------
__device__ __forceinline__ void build_rows(const float* __restrict__ src, int row0,
                                           float* __restrict__ Xs) {
    int k = threadIdx.x;
    #pragma unroll 4
    for (int m = 0; m < 64; m++) {
        int r = row0 + m; if (r > Nn - 1) r = Nn - 1;
        Xs[k*MP + m] = src[(size_t)r*Hh + k];
    }
}

__device__ __forceinline__ void gemm_core(const float* __restrict__ W,
                                          float* __restrict__ Xs,
                                          float* __restrict__ Ws,
                                          unsigned long long (&acc)[32]) {
    int tid = threadIdx.x;
    int nthr = tid & 63, mgrp = tid >> 6;
    const float4* Wg4 = (const float4*)W;
    float4* Ws4 = (float4*)Ws;
    for (int kt = 0; kt < Hh/KT; kt++) {
        __syncthreads();
        #pragma unroll
        for (int i = 0; i < (KT*64)/256; i++) {
            int idx = i*256 + tid;
            Ws4[idx] = Wg4[kt*(KT*64) + idx];
        }
        __syncthreads();
        #pragma unroll
        for (int kk = 0; kk < KT; kk++) {
            int k = kt*KT + kk;
            float4 w = Ws4[kk*64 + nthr];
            unsigned long long wd0 = dup2(w.x), wd1 = dup2(w.y),
                               wd2 = dup2(w.z), wd3 = dup2(w.w);
            const ulonglong2* xp = (const ulonglong2*)(Xs + k*MP + mgrp*16);
            #pragma unroll
            for (int j = 0; j < 4; j++) {
                ulonglong2 tp = xp[j];
                fma2(acc[(2*j)*4+0],   tp.x, wd0);
                fma2(acc[(2*j)*4+1],   tp.x, wd1);
                fma2(acc[(2*j)*4+2],   tp.x, wd2);
                fma2(acc[(2*j)*4+3],   tp.x, wd3);
                fma2(acc[(2*j+1)*4+0], tp.y, wd0);
                fma2(acc[(2*j+1)*4+1], tp.y, wd1);
                fma2(acc[(2*j+1)*4+2], tp.y, wd2);
                fma2(acc[(2*j+1)*4+3], tp.y, wd3);
            }
        }
    }
}

__device__ __forceinline__ void unpack_pair(const unsigned long long (&acc)[32], int p,
                                            float4& v0, float4& v1) {
    unpack2(acc[p*4+0], v0.x, v1.x);
    unpack2(acc[p*4+1], v0.y, v1.y);
    unpack2(acc[p*4+2], v0.z, v1.z);
    unpack2(acc[p*4+3], v0.w, v1.w);
}

// ---------------- per-layer LUT vectors ----------------------------------------
__global__ void k_lut(const float* __restrict__ rel_embs, const float* __restrict__ role_embs,
                      const float* __restrict__ col_embs,
                      const float* __restrict__ e1w, const float* __restrict__ e1b,
                      const float* __restrict__ n1w, const float* __restrict__ n1b, int li) {
    int n = threadIdx.x;
    int b = blockIdx.x;
    const float* e1wl = e1w + (size_t)li*560*Hh;
    const float* n1wl = n1w + (size_t)li*528*Hh;
    float acc = 0.f; const float* emb; const float* W; int kd;
    if (b < 8)       { emb = rel_embs  + (li*8 + b)     *16; W = e1wl + 512*Hh; kd = 16; acc = e1b[li*Hh + n]; }
    else if (b < 16) { emb = role_embs + (li*8 + (b-8)) *8;  W = e1wl + 528*Hh; kd = 8; }
    else if (b < 24) { emb = role_embs + (li*8 + (b-16))*8;  W = e1wl + 536*Hh; kd = 8; }
    else if (b < 27) { emb = col_embs  + (li*3 + (b-24))*8;  W = e1wl + 544*Hh; kd = 8; }
    else if (b < 30) { emb = col_embs  + (li*3 + (b-27))*8;  W = e1wl + 552*Hh; kd = 8; }
    else if (b < 38) { emb = role_embs + (li*8 + (b-30))*8;  W = n1wl + 512*Hh; kd = 8; acc = n1b[li*Hh + n]; }
    else             { emb = col_embs  + (li*3 + (b-38))*8;  W = n1wl + 520*Hh; kd = 8; }
    for (int k = 0; k < kd; k++) acc += emb[k]*W[k*Hh + n];
    g_lut[b*Hh + n] = acc;
}

// ---------------- node MLP second linear + residual + LayerNorm (FFMA) ---------
__global__ void __launch_bounds__(256,2)
k_n2(const float* __restrict__ n2w, const float* __restrict__ n2b,
     const float* __restrict__ lng, const float* __restrict__ lnb, int li) {
    extern __shared__ float sm[];
    float* Xs = sm;
    float* Ws = sm + 256*MP;
    __shared__ float mus[64], rss[64];
    int tid = threadIdx.x;
    int row0 = blockIdx.x * 64;
    build_rows(g_U, row0, Xs);
    unsigned long long acc[32];
    #pragma unroll
    for (int i = 0; i < 32; i++) acc[i] = 0ull;
    gemm_core(n2w + (size_t)li*Hh*Hh, Xs, Ws, acc);
    __syncthreads();
    float* xs = sm;                          // reuse as [64][260]
    int nthr = tid & 63, mgrp = tid >> 6, n0 = nthr*4;
    float4 bb = *(const float4*)(n2b + li*Hh + n0);
    #pragma unroll
    for (int p = 0; p < 8; p++) {
        float4 vv[2];
        unpack_pair(acc, p, vv[0], vv[1]);
        #pragma unroll
        for (int h = 0; h < 2; h++) {
            int m = mgrp*16 + 2*p + h; int node = row0 + m;
            int nc = (node > Nn-1) ? Nn-1 : node;
            float4 hv = *(const float4*)(g_h + (size_t)nc*Hh + n0);
            float4 v = vv[h];
            v.x += bb.x + hv.x; v.y += bb.y + hv.y; v.z += bb.z + hv.z; v.w += bb.w + hv.w;
            *(float4*)(xs + m*260 + n0) = v;
        }
    }
    __syncthreads();
    int lane = tid & 31, w = tid >> 5;
    for (int rrow = w*8; rrow < w*8 + 8; rrow++) {
        float s = 0.f, q = 0.f;
        #pragma unroll
        for (int j = 0; j < 8; j++) {
            float v = xs[rrow*260 + lane + j*32];
            s += v; q += v*v;
        }
        #pragma unroll
        for (int o = 16; o; o >>= 1) {
            s += __shfl_xor_sync(0xffffffffu, s, o);
            q += __shfl_xor_sync(0xffffffffu, q, o);
        }
        if (lane == 0) {
            float mu = s * (1.f/256.f);
            float var = q * (1.f/256.f) - mu*mu;
            mus[rrow] = mu;
            rss[rrow] = rsqrtf(fmaxf(var, 0.f) + 1e-5f);
        }
    }
    __syncthreads();
    for (int idx = tid; idx < 64*Hh; idx += 256) {
        int m = idx >> 8, n = idx & 255;
        int node = row0 + m;
        if (node < Nn) {
            float v = (xs[m*260 + n] - mus[m]) * rss[m] * lng[li*Hh + n] + lnb[li*Hh + n];
            g_h[(size_t)node*Hh + n] = v;
        }
    }
}

// ---------------- output projection (FFMA) --------------------------------------
__global__ void __launch_bounds__(256,2)
k_out(const float* __restrict__ outw, const float* __restrict__ outb, float* __restrict__ out) {
    extern __shared__ float sm[];
    float* Xs = sm;
    float* Ws = sm + 256*MP;
    int tid = threadIdx.x;
    int row0 = blockIdx.x * 64;
    build_rows(g_h, row0, Xs);
    int nthr = tid & 15, mgrp = tid >> 4, n0 = nthr*4;
    float4 acc[4];
    #pragma unroll
    for (int i = 0; i < 4; i++) acc[i] = make_float4(0.f,0.f,0.f,0.f);
    const float4* Wg4 = (const float4*)outw;
    float4* Ws4 = (float4*)Ws;
    for (int kt = 0; kt < 8; kt++) {
        __syncthreads();
        Ws4[tid]       = Wg4[kt*512 + tid];
        Ws4[256 + tid] = Wg4[kt*512 + 256 + tid];
        __syncthreads();
        #pragma unroll
        for (int kk = 0; kk < KT; kk++) {
            int k = kt*KT + kk;
            float4 w = Ws4[kk*16 + nthr];
            float4 t = *(const float4*)(Xs + k*MP + mgrp*4);
            acc[0].x += t.x*w.x; acc[0].y += t.x*w.y; acc[0].z += t.x*w.z; acc[0].w += t.x*w.w;
            acc[1].x += t.y*w.x; acc[1].y += t.y*w.y; acc[1].z += t.y*w.z; acc[1].w += t.y*w.w;
            acc[2].x += t.z*w.x; acc[2].y += t.z*w.y; acc[2].z += t.z*w.z; acc[2].w += t.z*w.w;
            acc[3].x += t.w*w.x; acc[3].y += t.w*w.y; acc[3].z += t.w*w.z; acc[3].w += t.w*w.w;
        }
    }
    float4 bb = *(const float4*)(outb + n0);
    #pragma unroll
    for (int i = 0; i < 4; i++) {
        int node = row0 + mgrp*4 + i;
        if (node < Nn) {
            float4 v = acc[i];
            v.x += bb.x; v.y += bb.y; v.z += bb.z; v.w += bb.w;
            *(float4*)(out + (size_t)node*64 + n0) = v;
        }
    }
}

// ---------------- launcher ------------------------------------------------------
extern "C" void kernel_launch(void* const* d_in, const int* in_sizes, int n_in,
                              void* d_out, int out_size) {
    const float* scalars      = (const float*)d_in[0];
    const int*   eidx         = (const int*)  d_in[1];
    const int*   erel         = (const int*)  d_in[2];
    const int*   ncol         = (const int*)  d_in[3];
    const int*   nrole        = (const int*)  d_in[4];
    const float* blk_role_emb = (const float*)d_in[5];
    const float* blk_col_emb  = (const float*)d_in[6];
    const float* in_w         = (const float*)d_in[7];
    const float* in_b         = (const float*)d_in[8];
    const float* rel_embs     = (const float*)d_in[9];
    const float* role_embs    = (const float*)d_in[10];
    const float* col_embs     = (const float*)d_in[11];
    const float* e1_w         = (const float*)d_in[12];
    const float* e1_b         = (const float*)d_in[13];
    const float* e2_w         = (const float*)d_in[14];
    const float* e2_b         = (const float*)d_in[15];
    const float* n1_w         = (const float*)d_in[16];
    const float* n1_b         = (const float*)d_in[17];
    const float* n2_w         = (const float*)d_in[18];
    const float* n2_b         = (const float*)d_in[19];
    const float* ln_g         = (const float*)d_in[20];
    const float* ln_b         = (const float*)d_in[21];
    const float* out_w        = (const float*)d_in[22];
    const float* out_b        = (const float*)d_in[23];
    const int* esrc = eidx;
    const int* edst = eidx + Ee;

    size_t sm_gemm = (size_t)(256*MP + KT*256) * sizeof(float);  // 102400 B
    size_t sm_out  = (size_t)(256*MP + KT*64)  * sizeof(float);
    cudaFuncSetAttribute(k_n2,       cudaFuncAttributeMaxDynamicSharedMemorySize, (int)sm_gemm);
    cudaFuncSetAttribute(k_out,      cudaFuncAttributeMaxDynamicSharedMemorySize, (int)sm_out);
    cudaFuncSetAttribute(k_edge_mma, cudaFuncAttributeMaxDynamicSharedMemorySize, SMEM_TC);
    cudaFuncSetAttribute(k_pq_mma,   cudaFuncAttributeMaxDynamicSharedMemorySize, SMEM_TC);
    cudaFuncSetAttribute(k_n1_mma,   cudaFuncAttributeMaxDynamicSharedMemorySize, SMEM_TC);

    int nb = (Nn + 63) / 64;  // 782

    k_prep<<<NB_IN + NB_W, 256>>>(scalars, ncol, nrole, blk_col_emb, blk_role_emb,
                                  in_w, in_b, e2_w, e1_w, n1_w);

    for (int li = 0; li < NLAYERS; li++) {
        k_lut<<<41, 256>>>(rel_embs, role_embs, col_embs, e1_w, e1_b, n1_w, n1_b, li);
        k_pq_mma<<<nb, 256, SMEM_TC>>>(nrole, ncol, li);
        // launch #4 in the stream -> the one ncu captures
        k_edge_mma<<<Ee/64, 256, SMEM_TC>>>(esrc, edst, erel, e2_b, li);
        k_n1_mma<<<nb, 256, SMEM_TC>>>(nrole, ncol, li);
        k_n2<<<nb, 256, sm_gemm>>>(n2_w, n2_b, ln_g, ln_b, li);
    }
    k_out<<<nb, 256, sm_out>>>(out_w, out_b, (float*)d_out);
}

// round 16
// speedup vs baseline: 1.5693x; 1.5693x over previous
#include <cuda_runtime.h>
#include <cuda_bf16.h>
#include <cstdint>

#define Nn 50000
#define Ee 800000
#define Hh 256
#define NLAYERS 3
#define MP 68     // Xs row stride (floats) for FFMA kernels
#define KT 32     // K tile (FFMA path)
#define NB_IN 782 // input-projection blocks inside k_prep
#define NB_W  3840 // weight-fragmentize blocks (3 layers x 5 sets x 65536 / 256)

// ---------------- scratch (no allocs allowed -> device globals) ----------------
static __device__ float g_h  [(size_t)Nn*Hh];
static __device__ float g_P  [(size_t)Nn*Hh];
static __device__ float g_Q  [(size_t)Nn*Hh];
static __device__ float g_agg[(size_t)Nn*Hh];
static __device__ float g_U  [(size_t)Nn*Hh];
static __device__ float g_lut[41*Hh];
// weights (hi split) in mma-fragment order, 5 sets per layer:
// which: 0=e2(edge), 1=e1 P, 2=e1 Q, 3=n1 h, 4=n1 agg
// [li][which][s=k/16][jp=n/16][lane][tb][word][half]  (uint4 per lane)
static __device__ __nv_bfloat16 g_wF[(size_t)3*5*16*16*32*8];

#define LUT_REL  0
#define LUT_RS   (8*Hh)
#define LUT_RD   (16*Hh)
#define LUT_CS   (24*Hh)
#define LUT_CD   (27*Hh)
#define LUT_NR   (30*Hh)
#define LUT_NC   (38*Hh)

__device__ __forceinline__ float silu_f(float x) {
    return __fdividef(x, 1.0f + __expf(-x));
}
__device__ __forceinline__ void red_add_v4(float* p, float4 v) {
    asm volatile("red.global.add.v4.f32 [%0], {%1,%2,%3,%4};"
                 :: "l"(p), "f"(v.x), "f"(v.y), "f"(v.z), "f"(v.w) : "memory");
}
__device__ __forceinline__ uint32_t smem_u32(const void* p) {
    uint32_t a;
    asm("{ .reg .u64 t; cvta.to.shared.u64 t, %1; cvt.u32.u64 %0, t; }" : "=r"(a) : "l"(p));
    return a;
}

// ---- Ampere-path tensor ops (plain sm_103-legal) ----
__device__ __forceinline__ void ldsm4(uint32_t (&r)[4], uint32_t addr) {
    asm volatile("ldmatrix.sync.aligned.m8n8.x4.shared.b16 {%0,%1,%2,%3}, [%4];"
                 : "=r"(r[0]), "=r"(r[1]), "=r"(r[2]), "=r"(r[3]) : "r"(addr));
}
__device__ __forceinline__ void mma16816(float (&d)[4], const uint32_t (&a)[4],
                                         uint32_t b0, uint32_t b1) {
    asm volatile(
        "mma.sync.aligned.m16n8k16.row.col.f32.bf16.bf16.f32 "
        "{%0,%1,%2,%3}, {%4,%5,%6,%7}, {%8,%9}, {%0,%1,%2,%3};"
        : "+f"(d[0]), "+f"(d[1]), "+f"(d[2]), "+f"(d[3])
        : "r"(a[0]), "r"(a[1]), "r"(a[2]), "r"(a[3]), "r"(b0), "r"(b1));
}

// packed f32x2 helpers (FFMA2 path: k_n2 / k_out)
__device__ __forceinline__ unsigned long long dup2(float x) {
    unsigned long long r;
    asm("mov.b64 %0, {%1,%1};" : "=l"(r) : "f"(x));
    return r;
}
__device__ __forceinline__ void fma2(unsigned long long& a, unsigned long long t,
                                     unsigned long long w) {
    asm("fma.rn.f32x2 %0, %1, %2, %0;" : "+l"(a) : "l"(t), "l"(w));
}
__device__ __forceinline__ void unpack2(unsigned long long u, float& a, float& b) {
    asm("mov.b64 {%0,%1}, %2;" : "=f"(a), "=f"(b) : "l"(u));
}

// ---------------- merged prep kernel: input projection + weight fragmentize ----
__global__ void k_prep(const float* __restrict__ scalars,
                       const int* __restrict__ colr, const int* __restrict__ role,
                       const float* __restrict__ cemb, const float* __restrict__ remb,
                       const float* __restrict__ in_w, const float* __restrict__ in_b,
                       const float* __restrict__ e2w, const float* __restrict__ e1w,
                       const float* __restrict__ n1w) {
    if (blockIdx.x < NB_IN) {
        int node0 = blockIdx.x * 64;
        int n = threadIdx.x;
        for (int mi = 0; mi < 64; mi++) {
            int node = node0 + mi;
            if (node >= Nn) return;
            float acc = in_b[n];
            const float* s = scalars + (size_t)node*16;
            #pragma unroll
            for (int k = 0; k < 16; k++) acc += s[k]*in_w[k*Hh + n];
            const float* ce = cemb + colr[node]*8;
            #pragma unroll
            for (int k = 0; k < 8; k++) acc += ce[k]*in_w[(16+k)*Hh + n];
            const float* re = remb + role[node]*8;
            #pragma unroll
            for (int k = 0; k < 8; k++) acc += re[k]*in_w[(24+k)*Hh + n];
            g_h[(size_t)node*Hh + n] = acc;
        }
    } else {
        int idx = (blockIdx.x - NB_IN) * 256 + threadIdx.x;
        if (idx >= 3*5*65536) return;
        int li = idx / (5*65536);
        int r = idx % (5*65536);
        int which = r >> 16;
        int t = r & 65535;
        int k = t >> 8, n = t & 255;
        float w;
        if      (which == 0) w = e2w[(size_t)li*65536 + k*256 + n];
        else if (which == 1) w = e1w[(size_t)li*560*256 + k*256 + n];
        else if (which == 2) w = e1w[(size_t)li*560*256 + (size_t)(k+256)*256 + n];
        else if (which == 3) w = n1w[(size_t)li*528*256 + k*256 + n];
        else                 w = n1w[(size_t)li*528*256 + (size_t)(k+256)*256 + n];
        __nv_bfloat16 hi = __float2bfloat16(w);
        int s = k >> 4, jp = n >> 4, tb = (n >> 3) & 1;
        int lane = ((n & 7) << 2) | ((k & 7) >> 1);
        int word = (k >> 3) & 1, half = k & 1;
        size_t bi = (((size_t)(li*5 + which)*16 + s)*16 + jp)*32 + lane;
        g_wF[bi*8 + tb*4 + word*2 + half] = hi;
    }
}

// ---------------- shared HMMA machinery (node kernels, 256-thread) -------------
#define EOFF_IDX  0
#define EOFF_BIAS 768
#define EOFF_AHI  1792                    // 64*528 = 33792
#define EOFF_ALO  (1792 + 33792)          // 35584
#define ASTRIDE   528
#define SMEM_TC   (35584 + 33792)         // 69376

// 16 k-steps of the 2-term mainloop for one 128-col output half.
__device__ __forceinline__ void tc_mainloop(uint32_t ahi_base, uint32_t alo_base,
                                            const uint4* __restrict__ whi, int jp0,
                                            float (&acc)[2][4][4]) {
    #pragma unroll
    for (int s = 0; s < 16; s++) {
        int kg = s * 16;
        uint32_t ah[2][4], al[2][4];
        ldsm4(ah[0], ahi_base + kg*2);
        ldsm4(ah[1], ahi_base + 16*ASTRIDE + kg*2);
        ldsm4(al[0], alo_base + kg*2);
        ldsm4(al[1], alo_base + 16*ASTRIDE + kg*2);
        uint4 bh0 = whi[(s*16 + jp0    )*32];
        uint4 bh1 = whi[(s*16 + jp0 + 1)*32];
        #pragma unroll
        for (int mt = 0; mt < 2; mt++) {
            mma16816(acc[mt][0], ah[mt], bh0.x, bh0.y);
            mma16816(acc[mt][1], ah[mt], bh0.z, bh0.w);
            mma16816(acc[mt][2], ah[mt], bh1.x, bh1.y);
            mma16816(acc[mt][3], ah[mt], bh1.z, bh1.w);
        }
        #pragma unroll
        for (int mt = 0; mt < 2; mt++) {
            mma16816(acc[mt][0], al[mt], bh0.x, bh0.y);
            mma16816(acc[mt][1], al[mt], bh0.z, bh0.w);
            mma16816(acc[mt][2], al[mt], bh1.x, bh1.y);
            mma16816(acc[mt][3], al[mt], bh1.z, bh1.w);
        }
    }
}

// build A hi/lo from contiguous node rows (64 rows, 256 threads)
__device__ __forceinline__ void build_A_node(float* __restrict__ src, int row0,
                                             char* __restrict__ smem, bool clear) {
    int tid = threadIdx.x;
    int k0 = (tid & 127) * 2, mh = tid >> 7;
    char* ahi = smem + EOFF_AHI;
    char* alo = smem + EOFF_ALO;
    #pragma unroll 4
    for (int m = mh*32; m < mh*32 + 32; m++) {
        int node = row0 + m; if (node > Nn-1) node = Nn-1;
        float2 v = *(const float2*)(src + (size_t)node*256 + k0);
        __nv_bfloat16 h0 = __float2bfloat16(v.x), h1 = __float2bfloat16(v.y);
        uint32_t hw = ((uint32_t)__bfloat16_as_ushort(h1) << 16)
                    | (uint32_t)__bfloat16_as_ushort(h0);
        float r0 = v.x - __bfloat162float(h0), r1 = v.y - __bfloat162float(h1);
        uint32_t lw;
        asm("cvt.rn.bf16x2.f32 %0, %1, %2;" : "=r"(lw) : "f"(r1), "f"(r0));
        *(uint32_t*)(ahi + m*ASTRIDE + k0*2) = hw;
        *(uint32_t*)(alo + m*ASTRIDE + k0*2) = lw;
        if (clear) *(float2*)(src + (size_t)node*256 + k0) = make_float2(0.f, 0.f);
    }
}

// ---------------- HMMA edge kernel (R12 configuration) --------------------------
__global__ void __launch_bounds__(256, 2)
k_edge_mma(const int* __restrict__ src, const int* __restrict__ dst,
           const int* __restrict__ rel, const float* __restrict__ e2b, int li) {
    extern __shared__ char smem[];
    uint32_t sb = smem_u32(smem);
    int tid = threadIdx.x, wid = tid >> 5, lane = tid & 31;
    int* ss = (int*)(smem + EOFF_IDX);
    int* ds = ss + 64;
    int* rr = ds + 64;
    float* bias = (float*)(smem + EOFF_BIAS);
    int e0 = blockIdx.x * 64;

    if (tid < 64) { ss[tid] = src[e0+tid]; ds[tid] = dst[e0+tid]; rr[tid] = rel[e0+tid]; }
    bias[tid] = e2b[li*256 + tid];
    __syncthreads();

    // build A hi/lo [m][k] from gathered P/Q/lut + silu
    {
        int k0 = (tid & 127) * 2, mh = tid >> 7;
        char* ahi = smem + EOFF_AHI;
        char* alo = smem + EOFF_ALO;
        #pragma unroll 4
        for (int m = mh*32; m < mh*32 + 32; m++) {
            int si = ss[m], di = ds[m], ri = rr[m];
            float2 p = *(const float2*)(g_P + (size_t)si*256 + k0);
            float2 q = *(const float2*)(g_Q + (size_t)di*256 + k0);
            float2 l = *(const float2*)(g_lut + LUT_REL + ri*256 + k0);
            float v0 = silu_f(p.x + q.x + l.x);
            float v1 = silu_f(p.y + q.y + l.y);
            __nv_bfloat16 h0 = __float2bfloat16(v0), h1 = __float2bfloat16(v1);
            uint32_t hw = ((uint32_t)__bfloat16_as_ushort(h1) << 16)
                        | (uint32_t)__bfloat16_as_ushort(h0);
            float r0 = v0 - __bfloat162float(h0), r1 = v1 - __bfloat162float(h1);
            uint32_t lw;
            asm("cvt.rn.bf16x2.f32 %0, %1, %2;" : "=r"(lw) : "f"(r1), "f"(r0));
            *(uint32_t*)(ahi + m*ASTRIDE + k0*2) = hw;
            *(uint32_t*)(alo + m*ASTRIDE + k0*2) = lw;
        }
    }
    __syncthreads();

    int wm = wid >> 2, wn = wid & 3;
    int a_row = (lane & 15), a_col = (lane >> 4) << 3;
    uint32_t ahi_base = sb + EOFF_AHI + (wm*32 + a_row)*ASTRIDE + a_col*2;
    uint32_t alo_base = sb + EOFF_ALO + (wm*32 + a_row)*ASTRIDE + a_col*2;
    const uint4* whi = ((const uint4*)g_wF) + (size_t)(li*5 + 0)*8192 + lane;

    #pragma unroll
    for (int nh = 0; nh < 2; nh++) {
        float acc[2][4][4];
        #pragma unroll
        for (int a = 0; a < 2; a++)
            #pragma unroll
            for (int b = 0; b < 4; b++)
                #pragma unroll
                for (int c = 0; c < 4; c++) acc[a][b][c] = 0.f;
        tc_mainloop(ahi_base, alo_base, whi, nh*8 + wn*2, acc);

        #pragma unroll
        for (int mt = 0; mt < 2; mt++) {
            int mlo = wm*32 + mt*16 + (lane >> 2);
            int mhi = mlo + 8;
            float* rowlo = g_agg + (size_t)ds[mlo] * 256;
            float* rowhi = g_agg + (size_t)ds[mhi] * 256;
            #pragma unroll
            for (int nt = 0; nt < 4; nt++) {
                int col = nh*128 + wn*32 + nt*8 + (lane & 3)*2;
                float s0 = silu_f(acc[mt][nt][0] + bias[col]);
                float s1 = silu_f(acc[mt][nt][1] + bias[col+1]);
                float s2 = silu_f(acc[mt][nt][2] + bias[col]);
                float s3 = silu_f(acc[mt][nt][3] + bias[col+1]);
                float p0 = __shfl_xor_sync(0xffffffffu, s0, 1);
                float p1 = __shfl_xor_sync(0xffffffffu, s1, 1);
                float p2 = __shfl_xor_sync(0xffffffffu, s2, 1);
                float p3 = __shfl_xor_sync(0xffffffffu, s3, 1);
                if (!(lane & 1)) {
                    red_add_v4(rowlo + col, make_float4(s0, s1, p0, p1));
                    red_add_v4(rowhi + col, make_float4(s2, s3, p2, p3));
                }
            }
        }
    }
}

// ---------------- HMMA P/Q kernel: one A-build serves 4 output halves ----------
__global__ void __launch_bounds__(256, 2)
k_pq_mma(const int* __restrict__ role, const int* __restrict__ colr, int li) {
    extern __shared__ char smem[];
    uint32_t sb = smem_u32(smem);
    int tid = threadIdx.x, wid = tid >> 5, lane = tid & 31;
    int* rs = (int*)(smem + EOFF_IDX);
    int* cs = rs + 64;
    int row0 = blockIdx.x * 64;

    if (tid < 64) {
        int r = row0 + tid; if (r > Nn-1) r = Nn-1;
        rs[tid] = role[r]; cs[tid] = colr[r];
    }
    __syncthreads();
    build_A_node(g_h, row0, smem, false);
    __syncthreads();

    int wm = wid >> 2, wn = wid & 3;
    int a_row = (lane & 15), a_col = (lane >> 4) << 3;
    uint32_t ahi_base = sb + EOFF_AHI + (wm*32 + a_row)*ASTRIDE + a_col*2;
    uint32_t alo_base = sb + EOFF_ALO + (wm*32 + a_row)*ASTRIDE + a_col*2;

    #pragma unroll
    for (int half = 0; half < 4; half++) {
        int which = (half < 2) ? 1 : 2;     // P : Q
        int nh = half & 1;
        const uint4* whi = ((const uint4*)g_wF) + (size_t)(li*5 + which)*8192 + lane;
        float acc[2][4][4];
        #pragma unroll
        for (int a = 0; a < 2; a++)
            #pragma unroll
            for (int b = 0; b < 4; b++)
                #pragma unroll
                for (int c = 0; c < 4; c++) acc[a][b][c] = 0.f;
        tc_mainloop(ahi_base, alo_base, whi, nh*8 + wn*2, acc);

        float* out = (half < 2) ? g_P : g_Q;
        const float* lutR = g_lut + ((half < 2) ? LUT_RS : LUT_RD);
        const float* lutC = g_lut + ((half < 2) ? LUT_CS : LUT_CD);
        #pragma unroll
        for (int mt = 0; mt < 2; mt++) {
            #pragma unroll
            for (int hh = 0; hh < 2; hh++) {
                int m = wm*32 + mt*16 + (lane >> 2) + hh*8;
                int node = row0 + m;
                if (node >= Nn) continue;
                const float* lr = lutR + rs[m]*256;
                const float* lc = lutC + cs[m]*256;
                float* orow = out + (size_t)node*256;
                #pragma unroll
                for (int nt = 0; nt < 4; nt++) {
                    int col = nh*128 + wn*32 + nt*8 + (lane & 3)*2;
                    float2 l1 = *(const float2*)(lr + col);
                    float2 l2 = *(const float2*)(lc + col);
                    float2 v;
                    v.x = acc[mt][nt][hh*2+0] + l1.x + l2.x;
                    v.y = acc[mt][nt][hh*2+1] + l1.y + l2.y;
                    *(float2*)(orow + col) = v;
                }
            }
        }
    }
}

// ---------------- HMMA n1 kernel: K=512 (h then agg), clears agg ----------------
__global__ void __launch_bounds__(256, 2)
k_n1_mma(const int* __restrict__ role, const int* __restrict__ colr, int li) {
    extern __shared__ char smem[];
    uint32_t sb = smem_u32(smem);
    int tid = threadIdx.x, wid = tid >> 5, lane = tid & 31;
    int* rs = (int*)(smem + EOFF_IDX);
    int* cs = rs + 64;
    int row0 = blockIdx.x * 64;

    if (tid < 64) {
        int r = row0 + tid; if (r > Nn-1) r = Nn-1;
        rs[tid] = role[r]; cs[tid] = colr[r];
    }

    int wm = wid >> 2, wn = wid & 3;
    int a_row = (lane & 15), a_col = (lane >> 4) << 3;
    uint32_t ahi_base = sb + EOFF_AHI + (wm*32 + a_row)*ASTRIDE + a_col*2;
    uint32_t alo_base = sb + EOFF_ALO + (wm*32 + a_row)*ASTRIDE + a_col*2;

    #pragma unroll
    for (int nh = 0; nh < 2; nh++) {
        float acc[2][4][4];
        #pragma unroll
        for (int a = 0; a < 2; a++)
            #pragma unroll
            for (int b = 0; b < 4; b++)
                #pragma unroll
                for (int c = 0; c < 4; c++) acc[a][b][c] = 0.f;

        __syncthreads();
        build_A_node(g_h, row0, smem, false);
        __syncthreads();
        {
            const uint4* whi = ((const uint4*)g_wF) + (size_t)(li*5 + 3)*8192 + lane;
            tc_mainloop(ahi_base, alo_base, whi, nh*8 + wn*2, acc);
        }
        __syncthreads();
        build_A_node(g_agg, row0, smem, nh == 1);   // clear agg on last pass
        __syncthreads();
        {
            const uint4* whi = ((const uint4*)g_wF) + (size_t)(li*5 + 4)*8192 + lane;
            tc_mainloop(ahi_base, alo_base, whi, nh*8 + wn*2, acc);
        }

        #pragma unroll
        for (int mt = 0; mt < 2; mt++) {
            #pragma unroll
            for (int hh = 0; hh < 2; hh++) {
                int m = wm*32 + mt*16 + (lane >> 2) + hh*8;
                int node = row0 + m;
                if (node >= Nn) continue;
                const float* lr = g_lut + LUT_NR + rs[m]*256;
                const float* lc = g_lut + LUT_NC + cs[m]*256;
                float* orow = g_U + (size_t)node*256;
                #pragma unroll
                for (int nt = 0; nt < 4; nt++) {
                    int col = nh*128 + wn*32 + nt*8 + (lane & 3)*2;
                    float2 l1 = *(const float2*)(lr + col);
                    float2 l2 = *(const float2*)(lc + col);
                    float2 v;
                    v.x = silu_f(acc[mt][nt][hh*2+0] + l1.x + l2.x);
                    v.y = silu_f(acc[mt][nt][hh*2+1] + l1.y + l2.y);
                    *(float2*)(orow + col) = v;
                }
            }
        }
    }
}

// ---------------- FFMA-path machinery (k_n2 / k_out) ----------------------------
__device__ __forceinline__ void build_rows(const float* __restrict__ src, int row0,
                                           float* __restrict__ Xs) {
    int k = threadIdx.x;
    #pragma unroll 4
    for (int m = 0; m < 64; m++) {
        int r = row0 + m; if (r > Nn - 1) r = Nn - 1;
        Xs[k*MP + m] = src[(size_t)r*Hh + k];
    }
}

__device__ __forceinline__ void gemm_core(const float* __restrict__ W,
                                          float* __restrict__ Xs,
                                          float* __restrict__ Ws,
                                          unsigned long long (&acc)[32]) {
    int tid = threadIdx.x;
    int nthr = tid & 63, mgrp = tid >> 6;
    const float4* Wg4 = (const float4*)W;
    float4* Ws4 = (float4*)Ws;
    for (int kt = 0; kt < Hh/KT; kt++) {
        __syncthreads();
        #pragma unroll
        for (int i = 0; i < (KT*64)/256; i++) {
            int idx = i*256 + tid;
            Ws4[idx] = Wg4[kt*(KT*64) + idx];
        }
        __syncthreads();
        #pragma unroll
        for (int kk = 0; kk < KT; kk++) {
            int k = kt*KT + kk;
            float4 w = Ws4[kk*64 + nthr];
            unsigned long long wd0 = dup2(w.x), wd1 = dup2(w.y),
                               wd2 = dup2(w.z), wd3 = dup2(w.w);
            const ulonglong2* xp = (const ulonglong2*)(Xs + k*MP + mgrp*16);
            #pragma unroll
            for (int j = 0; j < 4; j++) {
                ulonglong2 tp = xp[j];
                fma2(acc[(2*j)*4+0],   tp.x, wd0);
                fma2(acc[(2*j)*4+1],   tp.x, wd1);
                fma2(acc[(2*j)*4+2],   tp.x, wd2);
                fma2(acc[(2*j)*4+3],   tp.x, wd3);
                fma2(acc[(2*j+1)*4+0], tp.y, wd0);
                fma2(acc[(2*j+1)*4+1], tp.y, wd1);
                fma2(acc[(2*j+1)*4+2], tp.y, wd2);
                fma2(acc[(2*j+1)*4+3], tp.y, wd3);
            }
        }
    }
}

__device__ __forceinline__ void unpack_pair(const unsigned long long (&acc)[32], int p,
                                            float4& v0, float4& v1) {
    unpack2(acc[p*4+0], v0.x, v1.x);
    unpack2(acc[p*4+1], v0.y, v1.y);
    unpack2(acc[p*4+2], v0.z, v1.z);
    unpack2(acc[p*4+3], v0.w, v1.w);
}

// ---------------- per-layer LUT vectors ----------------------------------------
__global__ void k_lut(const float* __restrict__ rel_embs, const float* __restrict__ role_embs,
                      const float* __restrict__ col_embs,
                      const float* __restrict__ e1w, const float* __restrict__ e1b,
                      const float* __restrict__ n1w, const float* __restrict__ n1b, int li) {
    int n = threadIdx.x;
    int b = blockIdx.x;
    const float* e1wl = e1w + (size_t)li*560*Hh;
    const float* n1wl = n1w + (size_t)li*528*Hh;
    float acc = 0.f; const float* emb; const float* W; int kd;
    if (b < 8)       { emb = rel_embs  + (li*8 + b)     *16; W = e1wl + 512*Hh; kd = 16; acc = e1b[li*Hh + n]; }
    else if (b < 16) { emb = role_embs + (li*8 + (b-8)) *8;  W = e1wl + 528*Hh; kd = 8; }
    else if (b < 24) { emb = role_embs + (li*8 + (b-16))*8;  W = e1wl + 536*Hh; kd = 8; }
    else if (b < 27) { emb = col_embs  + (li*3 + (b-24))*8;  W = e1wl + 544*Hh; kd = 8; }
    else if (b < 30) { emb = col_embs  + (li*3 + (b-27))*8;  W = e1wl + 552*Hh; kd = 8; }
    else if (b < 38) { emb = role_embs + (li*8 + (b-30))*8;  W = n1wl + 512*Hh; kd = 8; acc = n1b[li*Hh + n]; }
    else             { emb = col_embs  + (li*3 + (b-38))*8;  W = n1wl + 520*Hh; kd = 8; }
    for (int k = 0; k < kd; k++) acc += emb[k]*W[k*Hh + n];
    g_lut[b*Hh + n] = acc;
}

// ---------------- node MLP second linear + residual + LayerNorm (FFMA) ---------
__global__ void __launch_bounds__(256,2)
k_n2(const float* __restrict__ n2w, const float* __restrict__ n2b,
     const float* __restrict__ lng, const float* __restrict__ lnb, int li) {
    extern __shared__ float sm[];
    float* Xs = sm;
    float* Ws = sm + 256*MP;
    __shared__ float mus[64], rss[64];
    int tid = threadIdx.x;
    int row0 = blockIdx.x * 64;
    build_rows(g_U, row0, Xs);
    unsigned long long acc[32];
    #pragma unroll
    for (int i = 0; i < 32; i++) acc[i] = 0ull;
    gemm_core(n2w + (size_t)li*Hh*Hh, Xs, Ws, acc);
    __syncthreads();
    float* xs = sm;                          // reuse as [64][260]
    int nthr = tid & 63, mgrp = tid >> 6, n0 = nthr*4;
    float4 bb = *(const float4*)(n2b + li*Hh + n0);
    #pragma unroll
    for (int p = 0; p < 8; p++) {
        float4 vv[2];
        unpack_pair(acc, p, vv[0], vv[1]);
        #pragma unroll
        for (int h = 0; h < 2; h++) {
            int m = mgrp*16 + 2*p + h; int node = row0 + m;
            int nc = (node > Nn-1) ? Nn-1 : node;
            float4 hv = *(const float4*)(g_h + (size_t)nc*Hh + n0);
            float4 v = vv[h];
            v.x += bb.x + hv.x; v.y += bb.y + hv.y; v.z += bb.z + hv.z; v.w += bb.w + hv.w;
            *(float4*)(xs + m*260 + n0) = v;
        }
    }
    __syncthreads();
    int lane = tid & 31, w = tid >> 5;
    for (int rrow = w*8; rrow < w*8 + 8; rrow++) {
        float s = 0.f, q = 0.f;
        #pragma unroll
        for (int j = 0; j < 8; j++) {
            float v = xs[rrow*260 + lane + j*32];
            s += v; q += v*v;
        }
        #pragma unroll
        for (int o = 16; o; o >>= 1) {
            s += __shfl_xor_sync(0xffffffffu, s, o);
            q += __shfl_xor_sync(0xffffffffu, q, o);
        }
        if (lane == 0) {
            float mu = s * (1.f/256.f);
            float var = q * (1.f/256.f) - mu*mu;
            mus[rrow] = mu;
            rss[rrow] = rsqrtf(fmaxf(var, 0.f) + 1e-5f);
        }
    }
    __syncthreads();
    for (int idx = tid; idx < 64*Hh; idx += 256) {
        int m = idx >> 8, n = idx & 255;
        int node = row0 + m;
        if (node < Nn) {
            float v = (xs[m*260 + n] - mus[m]) * rss[m] * lng[li*Hh + n] + lnb[li*Hh + n];
            g_h[(size_t)node*Hh + n] = v;
        }
    }
}

// ---------------- output projection (FFMA) --------------------------------------
__global__ void __launch_bounds__(256,2)
k_out(const float* __restrict__ outw, const float* __restrict__ outb, float* __restrict__ out) {
    extern __shared__ float sm[];
    float* Xs = sm;
    float* Ws = sm + 256*MP;
    int tid = threadIdx.x;
    int row0 = blockIdx.x * 64;
    build_rows(g_h, row0, Xs);
    int nthr = tid & 15, mgrp = tid >> 4, n0 = nthr*4;
    float4 acc[4];
    #pragma unroll
    for (int i = 0; i < 4; i++) acc[i] = make_float4(0.f,0.f,0.f,0.f);
    const float4* Wg4 = (const float4*)outw;
    float4* Ws4 = (float4*)Ws;
    for (int kt = 0; kt < 8; kt++) {
        __syncthreads();
        Ws4[tid]       = Wg4[kt*512 + tid];
        Ws4[256 + tid] = Wg4[kt*512 + 256 + tid];
        __syncthreads();
        #pragma unroll
        for (int kk = 0; kk < KT; kk++) {
            int k = kt*KT + kk;
            float4 w = Ws4[kk*16 + nthr];
            float4 t = *(const float4*)(Xs + k*MP + mgrp*4);
            acc[0].x += t.x*w.x; acc[0].y += t.x*w.y; acc[0].z += t.x*w.z; acc[0].w += t.x*w.w;
            acc[1].x += t.y*w.x; acc[1].y += t.y*w.y; acc[1].z += t.y*w.z; acc[1].w += t.y*w.w;
            acc[2].x += t.z*w.x; acc[2].y += t.z*w.y; acc[2].z += t.z*w.z; acc[2].w += t.z*w.w;
            acc[3].x += t.w*w.x; acc[3].y += t.w*w.y; acc[3].z += t.w*w.z; acc[3].w += t.w*w.w;
        }
    }
    float4 bb = *(const float4*)(outb + n0);
    #pragma unroll
    for (int i = 0; i < 4; i++) {
        int node = row0 + mgrp*4 + i;
        if (node < Nn) {
            float4 v = acc[i];
            v.x += bb.x; v.y += bb.y; v.z += bb.z; v.w += bb.w;
            *(float4*)(out + (size_t)node*64 + n0) = v;
        }
    }
}

// ---------------- launcher ------------------------------------------------------
extern "C" void kernel_launch(void* const* d_in, const int* in_sizes, int n_in,
                              void* d_out, int out_size) {
    const float* scalars      = (const float*)d_in[0];
    const int*   eidx         = (const int*)  d_in[1];
    const int*   erel         = (const int*)  d_in[2];
    const int*   ncol         = (const int*)  d_in[3];
    const int*   nrole        = (const int*)  d_in[4];
    const float* blk_role_emb = (const float*)d_in[5];
    const float* blk_col_emb  = (const float*)d_in[6];
    const float* in_w         = (const float*)d_in[7];
    const float* in_b         = (const float*)d_in[8];
    const float* rel_embs     = (const float*)d_in[9];
    const float* role_embs    = (const float*)d_in[10];
    const float* col_embs     = (const float*)d_in[11];
    const float* e1_w         = (const float*)d_in[12];
    const float* e1_b         = (const float*)d_in[13];
    const float* e2_w         = (const float*)d_in[14];
    const float* e2_b         = (const float*)d_in[15];
    const float* n1_w         = (const float*)d_in[16];
    const float* n1_b         = (const float*)d_in[17];
    const float* n2_w         = (const float*)d_in[18];
    const float* n2_b         = (const float*)d_in[19];
    const float* ln_g         = (const float*)d_in[20];
    const float* ln_b         = (const float*)d_in[21];
    const float* out_w        = (const float*)d_in[22];
    const float* out_b        = (const float*)d_in[23];
    const int* esrc = eidx;
    const int* edst = eidx + Ee;

    size_t sm_gemm = (size_t)(256*MP + KT*256) * sizeof(float);  // 102400 B
    size_t sm_out  = (size_t)(256*MP + KT*64)  * sizeof(float);
    cudaFuncSetAttribute(k_n2,       cudaFuncAttributeMaxDynamicSharedMemorySize, (int)sm_gemm);
    cudaFuncSetAttribute(k_out,      cudaFuncAttributeMaxDynamicSharedMemorySize, (int)sm_out);
    cudaFuncSetAttribute(k_edge_mma, cudaFuncAttributeMaxDynamicSharedMemorySize, SMEM_TC);
    cudaFuncSetAttribute(k_pq_mma,   cudaFuncAttributeMaxDynamicSharedMemorySize, SMEM_TC);
    cudaFuncSetAttribute(k_n1_mma,   cudaFuncAttributeMaxDynamicSharedMemorySize, SMEM_TC);

    int nb = (Nn + 63) / 64;  // 782

    k_prep<<<NB_IN + NB_W, 256>>>(scalars, ncol, nrole, blk_col_emb, blk_role_emb,
                                  in_w, in_b, e2_w, e1_w, n1_w);

    for (int li = 0; li < NLAYERS; li++) {
        k_lut<<<41, 256>>>(rel_embs, role_embs, col_embs, e1_w, e1_b, n1_w, n1_b, li);
        k_pq_mma<<<nb, 256, SMEM_TC>>>(nrole, ncol, li);
        // launch #4 in the stream -> the one ncu captures
        k_edge_mma<<<Ee/64, 256, SMEM_TC>>>(esrc, edst, erel, e2_b, li);
        k_n1_mma<<<nb, 256, SMEM_TC>>>(nrole, ncol, li);
        k_n2<<<nb, 256, sm_gemm>>>(n2_w, n2_b, ln_g, ln_b, li);
    }
    k_out<<<nb, 256, sm_out>>>(out_w, out_b, (float*)d_out);
}

// round 17
// speedup vs baseline: 1.7023x; 1.0848x over previous
#include <cuda_runtime.h>
#include <cuda_bf16.h>
#include <cstdint>

#define Nn 50000
#define Ee 800000
#define Hh 256
#define NLAYERS 3
#define MP 68     // Xs row stride (floats) for k_out
#define KT 32
#define NB_IN 782 // input-projection blocks inside k_prep
#define NB_W  4608 // weight-fragmentize blocks (3 layers x 6 sets x 65536 / 256)

// ---------------- scratch (no allocs allowed -> device globals) ----------------
static __device__ float g_h  [(size_t)Nn*Hh];
static __device__ float g_P  [(size_t)Nn*Hh];
static __device__ float g_Q  [(size_t)Nn*Hh];
static __device__ float g_agg[(size_t)Nn*Hh];
static __device__ float g_U  [(size_t)Nn*Hh];
static __device__ float g_lut[41*Hh];
// weights (hi split) in mma-fragment order, 6 sets per layer:
// which: 0=e2(edge), 1=e1 P, 2=e1 Q, 3=n1 h, 4=n1 agg, 5=n2
// [li][which][s=k/16][jp=n/16][lane][tb][word][half]  (uint4 per lane)
static __device__ __nv_bfloat16 g_wF[(size_t)3*6*16*16*32*8];

#define LUT_REL  0
#define LUT_RS   (8*Hh)
#define LUT_RD   (16*Hh)
#define LUT_CS   (24*Hh)
#define LUT_CD   (27*Hh)
#define LUT_NR   (30*Hh)
#define LUT_NC   (38*Hh)

__device__ __forceinline__ float silu_f(float x) {
    return __fdividef(x, 1.0f + __expf(-x));
}
__device__ __forceinline__ void red_add_v4(float* p, float4 v) {
    asm volatile("red.global.add.v4.f32 [%0], {%1,%2,%3,%4};"
                 :: "l"(p), "f"(v.x), "f"(v.y), "f"(v.z), "f"(v.w) : "memory");
}
__device__ __forceinline__ uint32_t smem_u32(const void* p) {
    uint32_t a;
    asm("{ .reg .u64 t; cvta.to.shared.u64 t, %1; cvt.u32.u64 %0, t; }" : "=r"(a) : "l"(p));
    return a;
}

// ---- Ampere-path tensor ops (plain sm_103-legal) ----
__device__ __forceinline__ void ldsm4(uint32_t (&r)[4], uint32_t addr) {
    asm volatile("ldmatrix.sync.aligned.m8n8.x4.shared.b16 {%0,%1,%2,%3}, [%4];"
                 : "=r"(r[0]), "=r"(r[1]), "=r"(r[2]), "=r"(r[3]) : "r"(addr));
}
__device__ __forceinline__ void mma16816(float (&d)[4], const uint32_t (&a)[4],
                                         uint32_t b0, uint32_t b1) {
    asm volatile(
        "mma.sync.aligned.m16n8k16.row.col.f32.bf16.bf16.f32 "
        "{%0,%1,%2,%3}, {%4,%5,%6,%7}, {%8,%9}, {%0,%1,%2,%3};"
        : "+f"(d[0]), "+f"(d[1]), "+f"(d[2]), "+f"(d[3])
        : "r"(a[0]), "r"(a[1]), "r"(a[2]), "r"(a[3]), "r"(b0), "r"(b1));
}

// ---------------- merged prep kernel: input projection + weight fragmentize ----
__global__ void k_prep(const float* __restrict__ scalars,
                       const int* __restrict__ colr, const int* __restrict__ role,
                       const float* __restrict__ cemb, const float* __restrict__ remb,
                       const float* __restrict__ in_w, const float* __restrict__ in_b,
                       const float* __restrict__ e2w, const float* __restrict__ e1w,
                       const float* __restrict__ n1w, const float* __restrict__ n2w) {
    if (blockIdx.x < NB_IN) {
        int node0 = blockIdx.x * 64;
        int n = threadIdx.x;
        for (int mi = 0; mi < 64; mi++) {
            int node = node0 + mi;
            if (node >= Nn) return;
            float acc = in_b[n];
            const float* s = scalars + (size_t)node*16;
            #pragma unroll
            for (int k = 0; k < 16; k++) acc += s[k]*in_w[k*Hh + n];
            const float* ce = cemb + colr[node]*8;
            #pragma unroll
            for (int k = 0; k < 8; k++) acc += ce[k]*in_w[(16+k)*Hh + n];
            const float* re = remb + role[node]*8;
            #pragma unroll
            for (int k = 0; k < 8; k++) acc += re[k]*in_w[(24+k)*Hh + n];
            g_h[(size_t)node*Hh + n] = acc;
        }
    } else {
        int idx = (blockIdx.x - NB_IN) * 256 + threadIdx.x;
        if (idx >= 3*6*65536) return;
        int li = idx / (6*65536);
        int r = idx % (6*65536);
        int which = r >> 16;
        int t = r & 65535;
        int k = t >> 8, n = t & 255;
        float w;
        if      (which == 0) w = e2w[(size_t)li*65536 + k*256 + n];
        else if (which == 1) w = e1w[(size_t)li*560*256 + k*256 + n];
        else if (which == 2) w = e1w[(size_t)li*560*256 + (size_t)(k+256)*256 + n];
        else if (which == 3) w = n1w[(size_t)li*528*256 + k*256 + n];
        else if (which == 4) w = n1w[(size_t)li*528*256 + (size_t)(k+256)*256 + n];
        else                 w = n2w[(size_t)li*65536 + k*256 + n];
        __nv_bfloat16 hi = __float2bfloat16(w);
        int s = k >> 4, jp = n >> 4, tb = (n >> 3) & 1;
        int lane = ((n & 7) << 2) | ((k & 7) >> 1);
        int word = (k >> 3) & 1, half = k & 1;
        size_t bi = (((size_t)(li*6 + which)*16 + s)*16 + jp)*32 + lane;
        g_wF[bi*8 + tb*4 + word*2 + half] = hi;
    }
}

// ---------------- shared HMMA machinery (256-thread node/edge kernels) ---------
#define EOFF_IDX  0
#define EOFF_BIAS 768
#define EOFF_AHI  1792                    // 64*528 = 33792
#define EOFF_ALO  (1792 + 33792)          // 35584
#define ASTRIDE   528
#define SMEM_TC   (35584 + 33792)         // 69376
// k_n2_mma: extra half-0 staging buffer after the A region
#define EOFF_X0   69376                   // 64*132*4 = 33792
#define SMEM_N2   (69376 + 33792)         // 103168

// 16 k-steps of the 2-term mainloop for one 128-col output half.
__device__ __forceinline__ void tc_mainloop(uint32_t ahi_base, uint32_t alo_base,
                                            const uint4* __restrict__ whi, int jp0,
                                            float (&acc)[2][4][4]) {
    #pragma unroll
    for (int s = 0; s < 16; s++) {
        int kg = s * 16;
        uint32_t ah[2][4], al[2][4];
        ldsm4(ah[0], ahi_base + kg*2);
        ldsm4(ah[1], ahi_base + 16*ASTRIDE + kg*2);
        ldsm4(al[0], alo_base + kg*2);
        ldsm4(al[1], alo_base + 16*ASTRIDE + kg*2);
        uint4 bh0 = whi[(s*16 + jp0    )*32];
        uint4 bh1 = whi[(s*16 + jp0 + 1)*32];
        #pragma unroll
        for (int mt = 0; mt < 2; mt++) {
            mma16816(acc[mt][0], ah[mt], bh0.x, bh0.y);
            mma16816(acc[mt][1], ah[mt], bh0.z, bh0.w);
            mma16816(acc[mt][2], ah[mt], bh1.x, bh1.y);
            mma16816(acc[mt][3], ah[mt], bh1.z, bh1.w);
        }
        #pragma unroll
        for (int mt = 0; mt < 2; mt++) {
            mma16816(acc[mt][0], al[mt], bh0.x, bh0.y);
            mma16816(acc[mt][1], al[mt], bh0.z, bh0.w);
            mma16816(acc[mt][2], al[mt], bh1.x, bh1.y);
            mma16816(acc[mt][3], al[mt], bh1.z, bh1.w);
        }
    }
}

// build A hi/lo from contiguous node rows (64 rows, 256 threads)
__device__ __forceinline__ void build_A_node(float* __restrict__ src, int row0,
                                             char* __restrict__ smem, bool clear) {
    int tid = threadIdx.x;
    int k0 = (tid & 127) * 2, mh = tid >> 7;
    char* ahi = smem + EOFF_AHI;
    char* alo = smem + EOFF_ALO;
    #pragma unroll 4
    for (int m = mh*32; m < mh*32 + 32; m++) {
        int node = row0 + m; if (node > Nn-1) node = Nn-1;
        float2 v = *(const float2*)(src + (size_t)node*256 + k0);
        __nv_bfloat16 h0 = __float2bfloat16(v.x), h1 = __float2bfloat16(v.y);
        uint32_t hw = ((uint32_t)__bfloat16_as_ushort(h1) << 16)
                    | (uint32_t)__bfloat16_as_ushort(h0);
        float r0 = v.x - __bfloat162float(h0), r1 = v.y - __bfloat162float(h1);
        uint32_t lw;
        asm("cvt.rn.bf16x2.f32 %0, %1, %2;" : "=r"(lw) : "f"(r1), "f"(r0));
        *(uint32_t*)(ahi + m*ASTRIDE + k0*2) = hw;
        *(uint32_t*)(alo + m*ASTRIDE + k0*2) = lw;
        if (clear) *(float2*)(src + (size_t)node*256 + k0) = make_float2(0.f, 0.f);
    }
}

// ---------------- HMMA edge kernel (R12 configuration, untouched) ---------------
__global__ void __launch_bounds__(256, 2)
k_edge_mma(const int* __restrict__ src, const int* __restrict__ dst,
           const int* __restrict__ rel, const float* __restrict__ e2b, int li) {
    extern __shared__ char smem[];
    uint32_t sb = smem_u32(smem);
    int tid = threadIdx.x, wid = tid >> 5, lane = tid & 31;
    int* ss = (int*)(smem + EOFF_IDX);
    int* ds = ss + 64;
    int* rr = ds + 64;
    float* bias = (float*)(smem + EOFF_BIAS);
    int e0 = blockIdx.x * 64;

    if (tid < 64) { ss[tid] = src[e0+tid]; ds[tid] = dst[e0+tid]; rr[tid] = rel[e0+tid]; }
    bias[tid] = e2b[li*256 + tid];
    __syncthreads();

    {
        int k0 = (tid & 127) * 2, mh = tid >> 7;
        char* ahi = smem + EOFF_AHI;
        char* alo = smem + EOFF_ALO;
        #pragma unroll 4
        for (int m = mh*32; m < mh*32 + 32; m++) {
            int si = ss[m], di = ds[m], ri = rr[m];
            float2 p = *(const float2*)(g_P + (size_t)si*256 + k0);
            float2 q = *(const float2*)(g_Q + (size_t)di*256 + k0);
            float2 l = *(const float2*)(g_lut + LUT_REL + ri*256 + k0);
            float v0 = silu_f(p.x + q.x + l.x);
            float v1 = silu_f(p.y + q.y + l.y);
            __nv_bfloat16 h0 = __float2bfloat16(v0), h1 = __float2bfloat16(v1);
            uint32_t hw = ((uint32_t)__bfloat16_as_ushort(h1) << 16)
                        | (uint32_t)__bfloat16_as_ushort(h0);
            float r0 = v0 - __bfloat162float(h0), r1 = v1 - __bfloat162float(h1);
            uint32_t lw;
            asm("cvt.rn.bf16x2.f32 %0, %1, %2;" : "=r"(lw) : "f"(r1), "f"(r0));
            *(uint32_t*)(ahi + m*ASTRIDE + k0*2) = hw;
            *(uint32_t*)(alo + m*ASTRIDE + k0*2) = lw;
        }
    }
    __syncthreads();

    int wm = wid >> 2, wn = wid & 3;
    int a_row = (lane & 15), a_col = (lane >> 4) << 3;
    uint32_t ahi_base = sb + EOFF_AHI + (wm*32 + a_row)*ASTRIDE + a_col*2;
    uint32_t alo_base = sb + EOFF_ALO + (wm*32 + a_row)*ASTRIDE + a_col*2;
    const uint4* whi = ((const uint4*)g_wF) + (size_t)(li*6 + 0)*8192 + lane;

    #pragma unroll
    for (int nh = 0; nh < 2; nh++) {
        float acc[2][4][4];
        #pragma unroll
        for (int a = 0; a < 2; a++)
            #pragma unroll
            for (int b = 0; b < 4; b++)
                #pragma unroll
                for (int c = 0; c < 4; c++) acc[a][b][c] = 0.f;
        tc_mainloop(ahi_base, alo_base, whi, nh*8 + wn*2, acc);

        #pragma unroll
        for (int mt = 0; mt < 2; mt++) {
            int mlo = wm*32 + mt*16 + (lane >> 2);
            int mhi = mlo + 8;
            float* rowlo = g_agg + (size_t)ds[mlo] * 256;
            float* rowhi = g_agg + (size_t)ds[mhi] * 256;
            #pragma unroll
            for (int nt = 0; nt < 4; nt++) {
                int col = nh*128 + wn*32 + nt*8 + (lane & 3)*2;
                float s0 = silu_f(acc[mt][nt][0] + bias[col]);
                float s1 = silu_f(acc[mt][nt][1] + bias[col+1]);
                float s2 = silu_f(acc[mt][nt][2] + bias[col]);
                float s3 = silu_f(acc[mt][nt][3] + bias[col+1]);
                float p0 = __shfl_xor_sync(0xffffffffu, s0, 1);
                float p1 = __shfl_xor_sync(0xffffffffu, s1, 1);
                float p2 = __shfl_xor_sync(0xffffffffu, s2, 1);
                float p3 = __shfl_xor_sync(0xffffffffu, s3, 1);
                if (!(lane & 1)) {
                    red_add_v4(rowlo + col, make_float4(s0, s1, p0, p1));
                    red_add_v4(rowhi + col, make_float4(s2, s3, p2, p3));
                }
            }
        }
    }
}

// ---------------- HMMA P/Q kernel (untouched) -----------------------------------
__global__ void __launch_bounds__(256, 2)
k_pq_mma(const int* __restrict__ role, const int* __restrict__ colr, int li) {
    extern __shared__ char smem[];
    uint32_t sb = smem_u32(smem);
    int tid = threadIdx.x, wid = tid >> 5, lane = tid & 31;
    int* rs = (int*)(smem + EOFF_IDX);
    int* cs = rs + 64;
    int row0 = blockIdx.x * 64;

    if (tid < 64) {
        int r = row0 + tid; if (r > Nn-1) r = Nn-1;
        rs[tid] = role[r]; cs[tid] = colr[r];
    }
    __syncthreads();
    build_A_node(g_h, row0, smem, false);
    __syncthreads();

    int wm = wid >> 2, wn = wid & 3;
    int a_row = (lane & 15), a_col = (lane >> 4) << 3;
    uint32_t ahi_base = sb + EOFF_AHI + (wm*32 + a_row)*ASTRIDE + a_col*2;
    uint32_t alo_base = sb + EOFF_ALO + (wm*32 + a_row)*ASTRIDE + a_col*2;

    #pragma unroll
    for (int half = 0; half < 4; half++) {
        int which = (half < 2) ? 1 : 2;     // P : Q
        int nh = half & 1;
        const uint4* whi = ((const uint4*)g_wF) + (size_t)(li*6 + which)*8192 + lane;
        float acc[2][4][4];
        #pragma unroll
        for (int a = 0; a < 2; a++)
            #pragma unroll
            for (int b = 0; b < 4; b++)
                #pragma unroll
                for (int c = 0; c < 4; c++) acc[a][b][c] = 0.f;
        tc_mainloop(ahi_base, alo_base, whi, nh*8 + wn*2, acc);

        float* out = (half < 2) ? g_P : g_Q;
        const float* lutR = g_lut + ((half < 2) ? LUT_RS : LUT_RD);
        const float* lutC = g_lut + ((half < 2) ? LUT_CS : LUT_CD);
        #pragma unroll
        for (int mt = 0; mt < 2; mt++) {
            #pragma unroll
            for (int hh = 0; hh < 2; hh++) {
                int m = wm*32 + mt*16 + (lane >> 2) + hh*8;
                int node = row0 + m;
                if (node >= Nn) continue;
                const float* lr = lutR + rs[m]*256;
                const float* lc = lutC + cs[m]*256;
                float* orow = out + (size_t)node*256;
                #pragma unroll
                for (int nt = 0; nt < 4; nt++) {
                    int col = nh*128 + wn*32 + nt*8 + (lane & 3)*2;
                    float2 l1 = *(const float2*)(lr + col);
                    float2 l2 = *(const float2*)(lc + col);
                    float2 v;
                    v.x = acc[mt][nt][hh*2+0] + l1.x + l2.x;
                    v.y = acc[mt][nt][hh*2+1] + l1.y + l2.y;
                    *(float2*)(orow + col) = v;
                }
            }
        }
    }
}

// ---------------- HMMA n1 kernel (untouched) ------------------------------------
__global__ void __launch_bounds__(256, 2)
k_n1_mma(const int* __restrict__ role, const int* __restrict__ colr, int li) {
    extern __shared__ char smem[];
    uint32_t sb = smem_u32(smem);
    int tid = threadIdx.x, wid = tid >> 5, lane = tid & 31;
    int* rs = (int*)(smem + EOFF_IDX);
    int* cs = rs + 64;
    int row0 = blockIdx.x * 64;

    if (tid < 64) {
        int r = row0 + tid; if (r > Nn-1) r = Nn-1;
        rs[tid] = role[r]; cs[tid] = colr[r];
    }

    int wm = wid >> 2, wn = wid & 3;
    int a_row = (lane & 15), a_col = (lane >> 4) << 3;
    uint32_t ahi_base = sb + EOFF_AHI + (wm*32 + a_row)*ASTRIDE + a_col*2;
    uint32_t alo_base = sb + EOFF_ALO + (wm*32 + a_row)*ASTRIDE + a_col*2;

    #pragma unroll
    for (int nh = 0; nh < 2; nh++) {
        float acc[2][4][4];
        #pragma unroll
        for (int a = 0; a < 2; a++)
            #pragma unroll
            for (int b = 0; b < 4; b++)
                #pragma unroll
                for (int c = 0; c < 4; c++) acc[a][b][c] = 0.f;

        __syncthreads();
        build_A_node(g_h, row0, smem, false);
        __syncthreads();
        {
            const uint4* whi = ((const uint4*)g_wF) + (size_t)(li*6 + 3)*8192 + lane;
            tc_mainloop(ahi_base, alo_base, whi, nh*8 + wn*2, acc);
        }
        __syncthreads();
        build_A_node(g_agg, row0, smem, nh == 1);   // clear agg on last pass
        __syncthreads();
        {
            const uint4* whi = ((const uint4*)g_wF) + (size_t)(li*6 + 4)*8192 + lane;
            tc_mainloop(ahi_base, alo_base, whi, nh*8 + wn*2, acc);
        }

        #pragma unroll
        for (int mt = 0; mt < 2; mt++) {
            #pragma unroll
            for (int hh = 0; hh < 2; hh++) {
                int m = wm*32 + mt*16 + (lane >> 2) + hh*8;
                int node = row0 + m;
                if (node >= Nn) continue;
                const float* lr = g_lut + LUT_NR + rs[m]*256;
                const float* lc = g_lut + LUT_NC + cs[m]*256;
                float* orow = g_U + (size_t)node*256;
                #pragma unroll
                for (int nt = 0; nt < 4; nt++) {
                    int col = nh*128 + wn*32 + nt*8 + (lane & 3)*2;
                    float2 l1 = *(const float2*)(lr + col);
                    float2 l2 = *(const float2*)(lc + col);
                    float2 v;
                    v.x = silu_f(acc[mt][nt][hh*2+0] + l1.x + l2.x);
                    v.y = silu_f(acc[mt][nt][hh*2+1] + l1.y + l2.y);
                    *(float2*)(orow + col) = v;
                }
            }
        }
    }
}

// ---------------- HMMA n2 kernel: GEMM + residual + LayerNorm -------------------
// nh=0 x-half staged to X0; nh=1 x-half staged into the (dead) AHI region;
// then the standard warp-per-8-rows LN over both regions -> g_h.
__global__ void __launch_bounds__(256, 2)
k_n2_mma(const float* __restrict__ n2b, const float* __restrict__ lng,
         const float* __restrict__ lnb, int li) {
    extern __shared__ char smem[];
    uint32_t sb = smem_u32(smem);
    int tid = threadIdx.x, wid = tid >> 5, lane = tid & 31;
    float* bias = (float*)(smem + EOFF_BIAS);
    float* x0 = (float*)(smem + EOFF_X0);      // [64][132] cols 0-127
    float* x1 = (float*)(smem + EOFF_AHI);     // [64][132] cols 128-255 (after A dead)
    __shared__ float mus[64], rss[64];
    int row0 = blockIdx.x * 64;

    bias[tid] = n2b[li*256 + tid];
    __syncthreads();                            // (also orders prior g_h readers)
    build_A_node(g_U, row0, smem, false);
    __syncthreads();

    int wm = wid >> 2, wn = wid & 3;
    int a_row = (lane & 15), a_col = (lane >> 4) << 3;
    uint32_t ahi_base = sb + EOFF_AHI + (wm*32 + a_row)*ASTRIDE + a_col*2;
    uint32_t alo_base = sb + EOFF_ALO + (wm*32 + a_row)*ASTRIDE + a_col*2;
    const uint4* whi = ((const uint4*)g_wF) + (size_t)(li*6 + 5)*8192 + lane;

    // nh = 0 -> stage x into X0
    {
        float acc[2][4][4];
        #pragma unroll
        for (int a = 0; a < 2; a++)
            #pragma unroll
            for (int b = 0; b < 4; b++)
                #pragma unroll
                for (int c = 0; c < 4; c++) acc[a][b][c] = 0.f;
        tc_mainloop(ahi_base, alo_base, whi, 0*8 + wn*2, acc);
        #pragma unroll
        for (int mt = 0; mt < 2; mt++) {
            #pragma unroll
            for (int hh = 0; hh < 2; hh++) {
                int m = wm*32 + mt*16 + (lane >> 2) + hh*8;
                int nc = row0 + m; if (nc > Nn-1) nc = Nn-1;
                #pragma unroll
                for (int nt = 0; nt < 4; nt++) {
                    int col = wn*32 + nt*8 + (lane & 3)*2;
                    float2 hv = *(const float2*)(g_h + (size_t)nc*256 + col);
                    float2 v;
                    v.x = acc[mt][nt][hh*2+0] + bias[col]   + hv.x;
                    v.y = acc[mt][nt][hh*2+1] + bias[col+1] + hv.y;
                    *(float2*)(x0 + m*132 + col) = v;
                }
            }
        }
    }
    // nh = 1 -> compute, then stage into AHI region (A dead after this mainloop)
    {
        float acc[2][4][4];
        #pragma unroll
        for (int a = 0; a < 2; a++)
            #pragma unroll
            for (int b = 0; b < 4; b++)
                #pragma unroll
                for (int c = 0; c < 4; c++) acc[a][b][c] = 0.f;
        tc_mainloop(ahi_base, alo_base, whi, 1*8 + wn*2, acc);
        __syncthreads();   // ALL warps done reading A before x1 overwrites it
        #pragma unroll
        for (int mt = 0; mt < 2; mt++) {
            #pragma unroll
            for (int hh = 0; hh < 2; hh++) {
                int m = wm*32 + mt*16 + (lane >> 2) + hh*8;
                int nc = row0 + m; if (nc > Nn-1) nc = Nn-1;
                #pragma unroll
                for (int nt = 0; nt < 4; nt++) {
                    int col = 128 + wn*32 + nt*8 + (lane & 3)*2;
                    float2 hv = *(const float2*)(g_h + (size_t)nc*256 + col);
                    float2 v;
                    v.x = acc[mt][nt][hh*2+0] + bias[col]   + hv.x;
                    v.y = acc[mt][nt][hh*2+1] + bias[col+1] + hv.y;
                    *(float2*)(x1 + m*132 + (col - 128)) = v;
                }
            }
        }
    }
    __syncthreads();

    // LayerNorm: warp w handles rows w*8 .. w*8+8
    int w = wid;
    for (int rrow = w*8; rrow < w*8 + 8; rrow++) {
        float s = 0.f, q = 0.f;
        #pragma unroll
        for (int j = 0; j < 8; j++) {
            int c = lane + j*32;
            float v = (c < 128) ? x0[rrow*132 + c] : x1[rrow*132 + (c - 128)];
            s += v; q += v*v;
        }
        #pragma unroll
        for (int o = 16; o; o >>= 1) {
            s += __shfl_xor_sync(0xffffffffu, s, o);
            q += __shfl_xor_sync(0xffffffffu, q, o);
        }
        if (lane == 0) {
            float mu = s * (1.f/256.f);
            float var = q * (1.f/256.f) - mu*mu;
            mus[rrow] = mu;
            rss[rrow] = rsqrtf(fmaxf(var, 0.f) + 1e-5f);
        }
    }
    __syncthreads();
    for (int idx = tid; idx < 64*256; idx += 256) {
        int m = idx >> 8, n = idx & 255;
        int node = row0 + m;
        if (node < Nn) {
            float xv = (n < 128) ? x0[m*132 + n] : x1[m*132 + (n - 128)];
            float v = (xv - mus[m]) * rss[m] * lng[li*256 + n] + lnb[li*256 + n];
            g_h[(size_t)node*256 + n] = v;
        }
    }
}

// ---------------- output projection (FFMA, untouched) ---------------------------
__device__ __forceinline__ void build_rows(const float* __restrict__ src, int row0,
                                           float* __restrict__ Xs) {
    int k = threadIdx.x;
    #pragma unroll 4
    for (int m = 0; m < 64; m++) {
        int r = row0 + m; if (r > Nn - 1) r = Nn - 1;
        Xs[k*MP + m] = src[(size_t)r*Hh + k];
    }
}

__global__ void __launch_bounds__(256,2)
k_out(const float* __restrict__ outw, const float* __restrict__ outb, float* __restrict__ out) {
    extern __shared__ float sm[];
    float* Xs = sm;
    float* Ws = sm + 256*MP;
    int tid = threadIdx.x;
    int row0 = blockIdx.x * 64;
    build_rows(g_h, row0, Xs);
    int nthr = tid & 15, mgrp = tid >> 4, n0 = nthr*4;
    float4 acc[4];
    #pragma unroll
    for (int i = 0; i < 4; i++) acc[i] = make_float4(0.f,0.f,0.f,0.f);
    const float4* Wg4 = (const float4*)outw;
    float4* Ws4 = (float4*)Ws;
    for (int kt = 0; kt < 8; kt++) {
        __syncthreads();
        Ws4[tid]       = Wg4[kt*512 + tid];
        Ws4[256 + tid] = Wg4[kt*512 + 256 + tid];
        __syncthreads();
        #pragma unroll
        for (int kk = 0; kk < KT; kk++) {
            int k = kt*KT + kk;
            float4 w = Ws4[kk*16 + nthr];
            float4 t = *(const float4*)(Xs + k*MP + mgrp*4);
            acc[0].x += t.x*w.x; acc[0].y += t.x*w.y; acc[0].z += t.x*w.z; acc[0].w += t.x*w.w;
            acc[1].x += t.y*w.x; acc[1].y += t.y*w.y; acc[1].z += t.y*w.z; acc[1].w += t.y*w.w;
            acc[2].x += t.z*w.x; acc[2].y += t.z*w.y; acc[2].z += t.z*w.z; acc[2].w += t.z*w.w;
            acc[3].x += t.w*w.x; acc[3].y += t.w*w.y; acc[3].z += t.w*w.z; acc[3].w += t.w*w.w;
        }
    }
    float4 bb = *(const float4*)(outb + n0);
    #pragma unroll
    for (int i = 0; i < 4; i++) {
        int node = row0 + mgrp*4 + i;
        if (node < Nn) {
            float4 v = acc[i];
            v.x += bb.x; v.y += bb.y; v.z += bb.z; v.w += bb.w;
            *(float4*)(out + (size_t)node*64 + n0) = v;
        }
    }
}

// ---------------- per-layer LUT vectors (untouched) -----------------------------
__global__ void k_lut(const float* __restrict__ rel_embs, const float* __restrict__ role_embs,
                      const float* __restrict__ col_embs,
                      const float* __restrict__ e1w, const float* __restrict__ e1b,
                      const float* __restrict__ n1w, const float* __restrict__ n1b, int li) {
    int n = threadIdx.x;
    int b = blockIdx.x;
    const float* e1wl = e1w + (size_t)li*560*Hh;
    const float* n1wl = n1w + (size_t)li*528*Hh;
    float acc = 0.f; const float* emb; const float* W; int kd;
    if (b < 8)       { emb = rel_embs  + (li*8 + b)     *16; W = e1wl + 512*Hh; kd = 16; acc = e1b[li*Hh + n]; }
    else if (b < 16) { emb = role_embs + (li*8 + (b-8)) *8;  W = e1wl + 528*Hh; kd = 8; }
    else if (b < 24) { emb = role_embs + (li*8 + (b-16))*8;  W = e1wl + 536*Hh; kd = 8; }
    else if (b < 27) { emb = col_embs  + (li*3 + (b-24))*8;  W = e1wl + 544*Hh; kd = 8; }
    else if (b < 30) { emb = col_embs  + (li*3 + (b-27))*8;  W = e1wl + 552*Hh; kd = 8; }
    else if (b < 38) { emb = role_embs + (li*8 + (b-30))*8;  W = n1wl + 512*Hh; kd = 8; acc = n1b[li*Hh + n]; }
    else             { emb = col_embs  + (li*3 + (b-38))*8;  W = n1wl + 520*Hh; kd = 8; }
    for (int k = 0; k < kd; k++) acc += emb[k]*W[k*Hh + n];
    g_lut[b*Hh + n] = acc;
}

// ---------------- launcher ------------------------------------------------------
extern "C" void kernel_launch(void* const* d_in, const int* in_sizes, int n_in,
                              void* d_out, int out_size) {
    const float* scalars      = (const float*)d_in[0];
    const int*   eidx         = (const int*)  d_in[1];
    const int*   erel         = (const int*)  d_in[2];
    const int*   ncol         = (const int*)  d_in[3];
    const int*   nrole        = (const int*)  d_in[4];
    const float* blk_role_emb = (const float*)d_in[5];
    const float* blk_col_emb  = (const float*)d_in[6];
    const float* in_w         = (const float*)d_in[7];
    const float* in_b         = (const float*)d_in[8];
    const float* rel_embs     = (const float*)d_in[9];
    const float* role_embs    = (const float*)d_in[10];
    const float* col_embs     = (const float*)d_in[11];
    const float* e1_w         = (const float*)d_in[12];
    const float* e1_b         = (const float*)d_in[13];
    const float* e2_w         = (const float*)d_in[14];
    const float* e2_b         = (const float*)d_in[15];
    const float* n1_w         = (const float*)d_in[16];
    const float* n1_b         = (const float*)d_in[17];
    const float* n2_w         = (const float*)d_in[18];
    const float* n2_b         = (const float*)d_in[19];
    const float* ln_g         = (const float*)d_in[20];
    const float* ln_b         = (const float*)d_in[21];
    const float* out_w        = (const float*)d_in[22];
    const float* out_b        = (const float*)d_in[23];
    const int* esrc = eidx;
    const int* edst = eidx + Ee;

    size_t sm_out  = (size_t)(256*MP + KT*64) * sizeof(float);
    cudaFuncSetAttribute(k_out,      cudaFuncAttributeMaxDynamicSharedMemorySize, (int)sm_out);
    cudaFuncSetAttribute(k_edge_mma, cudaFuncAttributeMaxDynamicSharedMemorySize, SMEM_TC);
    cudaFuncSetAttribute(k_pq_mma,   cudaFuncAttributeMaxDynamicSharedMemorySize, SMEM_TC);
    cudaFuncSetAttribute(k_n1_mma,   cudaFuncAttributeMaxDynamicSharedMemorySize, SMEM_TC);
    cudaFuncSetAttribute(k_n2_mma,   cudaFuncAttributeMaxDynamicSharedMemorySize, SMEM_N2);

    int nb = (Nn + 63) / 64;  // 782

    k_prep<<<NB_IN + NB_W, 256>>>(scalars, ncol, nrole, blk_col_emb, blk_role_emb,
                                  in_w, in_b, e2_w, e1_w, n1_w, n2_w);

    for (int li = 0; li < NLAYERS; li++) {
        k_lut<<<41, 256>>>(rel_embs, role_embs, col_embs, e1_w, e1_b, n1_w, n1_b, li);
        k_pq_mma<<<nb, 256, SMEM_TC>>>(nrole, ncol, li);
        // launch #4 in the stream -> the one ncu captures
        k_edge_mma<<<Ee/64, 256, SMEM_TC>>>(esrc, edst, erel, e2_b, li);
        k_n1_mma<<<nb, 256, SMEM_TC>>>(nrole, ncol, li);
        k_n2_mma<<<nb, 256, SMEM_N2>>>(n2_b, ln_g, ln_b, li);
    }
    k_out<<<nb, 256, sm_out>>>(out_w, out_b, (float*)d_out);
}